// round 5
// baseline (speedup 1.0000x reference)
#include <cuda_runtime.h>
#include <cuda_bf16.h>
#include <cstdint>

#define BATCH   32768
#define DIMD    128
#define NSTEPS  3
#define BN_EPS  1e-5f

typedef unsigned long long u64t;
union F2U { u64t u; float2 f; };

// fma.rn.f32x2: two independent fp32 FMAs in one instruction (sm_100+)
#define FMA2(acc, a, b) asm("fma.rn.f32x2 %0, %1, %2, %0;" : "+l"(acc) : "l"(a), "l"(b))

// ---------------- device scratch (no allocations allowed) ----------------
__device__ float g_sum[DIMD];
__device__ float g_sumsq[DIMD];
__device__ float g_mloss;
__device__ float g_xn[(size_t)BATCH * DIMD];          // normalized input (16 MB)
__device__ __align__(16) float g_wp[1474560];         // packed/duplicated weights (5.9 MB)

#define OFF_E0 0
#define OFF_E1 294912
#define OFF_D0 737280
#define OFF_D1 1032192

// ---------------- helpers ----------------
__device__ __forceinline__ float wsum(float v) {
#pragma unroll
    for (int o = 16; o > 0; o >>= 1) v += __shfl_xor_sync(0xffffffffu, v, o);
    return v;
}
__device__ __forceinline__ float wmax(float v) {
#pragma unroll
    for (int o = 16; o > 0; o >>= 1) v = fmaxf(v, __shfl_xor_sync(0xffffffffu, v, o));
    return v;
}
__device__ __forceinline__ float sigf(float x) {
    return 1.0f / (1.0f + __expf(-x));
}

// ---------------- GLU GEMM + GhostBN building block ----------------
// Activations stored as row-pairs: u64 slot at [k*64 + q] holds rows (p, p+64),
// q = (p&32) | ((p ^ (k&31)) & 31), p = row & 63 (XOR swizzle, conflict-free).
// One warp computes 4 GLU column-pairs (a-cols j0..j0+3, gates j0+192..) for all
// 128 rows. Lane owns row-pairs (lane, lane+64) and (lane+32, lane+96).
// Weights come pre-duplicated from g_wp: per (group,k) 16 floats =
//   {wa0,wa0,wa1,wa1,wa2,wa2,wa3,wa3, wg0,wg0,wg1,wg1,wg2,wg2,wg3,wg3}
// read as 4 uniform LDG.128 (broadcast), double-buffered.
// MODE 0: write GLU out to sOut2 (paired swizzled layout)
// MODE 1: write sigmoid(GLU out) to global outp (decoder final, cols 0..63)
// MODE 2: att update in sOut2: att = 1.3*sig(o)*(1 - max(att_old - tau, 0))
template<int K, int MODE>
__device__ __forceinline__ void glu_pass(
    const u64t* __restrict__ sA2,
    const ulonglong2* __restrict__ Wg,
    const float* __restrict__ gv, const float* __restrict__ bv,
    int j0, int lane,
    u64t* __restrict__ sOut2, const float* __restrict__ sTau,
    float* __restrict__ outp)
{
    u64t acc[8][2];
#pragma unroll
    for (int c = 0; c < 8; c++) { acc[c][0] = 0ull; acc[c][1] = 0ull; }

    ulonglong2 b0[4], b1[4];
#pragma unroll
    for (int q = 0; q < 4; q++) b0[q] = __ldg(Wg + q);
#pragma unroll
    for (int q = 0; q < 4; q++) b1[q] = __ldg(Wg + 4 + q);

#pragma unroll 1
    for (int kk = 0; kk < K; kk += 2) {
        {
            const int i0 = kk * 64 + (lane ^ (kk & 31));
            u64t xv0 = sA2[i0];
            u64t xv1 = sA2[i0 + 32];
            const int kn = (kk + 2 < K) ? (kk + 2) : 0;
            ulonglong2 n0 = __ldg(Wg + kn * 4 + 0);
            ulonglong2 n1 = __ldg(Wg + kn * 4 + 1);
            ulonglong2 n2 = __ldg(Wg + kn * 4 + 2);
            ulonglong2 n3 = __ldg(Wg + kn * 4 + 3);
            FMA2(acc[0][0], xv0, b0[0].x); FMA2(acc[0][1], xv1, b0[0].x);
            FMA2(acc[1][0], xv0, b0[0].y); FMA2(acc[1][1], xv1, b0[0].y);
            FMA2(acc[2][0], xv0, b0[1].x); FMA2(acc[2][1], xv1, b0[1].x);
            FMA2(acc[3][0], xv0, b0[1].y); FMA2(acc[3][1], xv1, b0[1].y);
            FMA2(acc[4][0], xv0, b0[2].x); FMA2(acc[4][1], xv1, b0[2].x);
            FMA2(acc[5][0], xv0, b0[2].y); FMA2(acc[5][1], xv1, b0[2].y);
            FMA2(acc[6][0], xv0, b0[3].x); FMA2(acc[6][1], xv1, b0[3].x);
            FMA2(acc[7][0], xv0, b0[3].y); FMA2(acc[7][1], xv1, b0[3].y);
            b0[0] = n0; b0[1] = n1; b0[2] = n2; b0[3] = n3;
        }
        {
            const int k1 = kk + 1;
            const int i0 = k1 * 64 + (lane ^ (k1 & 31));
            u64t xv0 = sA2[i0];
            u64t xv1 = sA2[i0 + 32];
            const int kn = (k1 + 2 < K) ? (k1 + 2) : 1;
            ulonglong2 n0 = __ldg(Wg + kn * 4 + 0);
            ulonglong2 n1 = __ldg(Wg + kn * 4 + 1);
            ulonglong2 n2 = __ldg(Wg + kn * 4 + 2);
            ulonglong2 n3 = __ldg(Wg + kn * 4 + 3);
            FMA2(acc[0][0], xv0, b1[0].x); FMA2(acc[0][1], xv1, b1[0].x);
            FMA2(acc[1][0], xv0, b1[0].y); FMA2(acc[1][1], xv1, b1[0].y);
            FMA2(acc[2][0], xv0, b1[1].x); FMA2(acc[2][1], xv1, b1[1].x);
            FMA2(acc[3][0], xv0, b1[1].y); FMA2(acc[3][1], xv1, b1[1].y);
            FMA2(acc[4][0], xv0, b1[2].x); FMA2(acc[4][1], xv1, b1[2].x);
            FMA2(acc[5][0], xv0, b1[2].y); FMA2(acc[5][1], xv1, b1[2].y);
            FMA2(acc[6][0], xv0, b1[3].x); FMA2(acc[6][1], xv1, b1[3].x);
            FMA2(acc[7][0], xv0, b1[3].y); FMA2(acc[7][1], xv1, b1[3].y);
            b1[0] = n0; b1[1] = n1; b1[2] = n2; b1[3] = n3;
        }
    }

    // extract: av[c][r], rows r -> lane + 32*r (r = i + 2*half)
    float av[8][4];
#pragma unroll
    for (int c = 0; c < 8; c++)
#pragma unroll
        for (int i = 0; i < 2; i++) {
            F2U t; t.u = acc[c][i];
            av[c][i]     = t.f.x;
            av[c][i + 2] = t.f.y;
        }

    // Ghost-BN per column (warp allreduce over 128 rows) + GLU
    float glu[4][4];
#pragma unroll
    for (int c = 0; c < 4; c++) {
        const int j = j0 + c;
        float s = wsum(av[c][0] + av[c][1] + av[c][2] + av[c][3]);
        float mean = s * (1.0f / 128.0f);
        float d0 = av[c][0]-mean, d1 = av[c][1]-mean, d2 = av[c][2]-mean, d3 = av[c][3]-mean;
        float v = wsum(d0*d0 + d1*d1 + d2*d2 + d3*d3);
        float rstd = rsqrtf(v * (1.0f / 128.0f) + BN_EPS);
        float ga = __ldg(gv + j) * rstd, ba = __ldg(bv + j);
        float s2 = wsum(av[4+c][0] + av[4+c][1] + av[4+c][2] + av[4+c][3]);
        float mean2 = s2 * (1.0f / 128.0f);
        float e0 = av[4+c][0]-mean2, e1 = av[4+c][1]-mean2, e2 = av[4+c][2]-mean2, e3 = av[4+c][3]-mean2;
        float v2 = wsum(e0*e0 + e1*e1 + e2*e2 + e3*e3);
        float rstd2 = rsqrtf(v2 * (1.0f / 128.0f) + BN_EPS);
        float gg = __ldg(gv + j + 192) * rstd2, bg = __ldg(bv + j + 192);
        glu[c][0] = (d0 * ga + ba) * sigf(e0 * gg + bg);
        glu[c][1] = (d1 * ga + ba) * sigf(e1 * gg + bg);
        glu[c][2] = (d2 * ga + ba) * sigf(e2 * gg + bg);
        glu[c][3] = (d3 * ga + ba) * sigf(e3 * gg + bg);
    }

    if (MODE == 0) {
#pragma unroll
        for (int c = 0; c < 4; c++) {
            const int j = j0 + c;
#pragma unroll
            for (int i = 0; i < 2; i++) {
                const int p = lane + 32 * i;
                F2U t; t.f.x = glu[c][i]; t.f.y = glu[c][i + 2];
                sOut2[j * 64 + ((p & 32) | ((p ^ (j & 31)) & 31))] = t.u;
            }
        }
    } else if (MODE == 1) {
#pragma unroll
        for (int r = 0; r < 4; r++) {
            const int row = lane + 32 * r;
            float4 o = make_float4(sigf(glu[0][r]), sigf(glu[1][r]),
                                   sigf(glu[2][r]), sigf(glu[3][r]));
            *(float4*)(outp + (size_t)row * 64 + j0) = o;
        }
    } else { // MODE 2: att update
#pragma unroll
        for (int c = 0; c < 4; c++) {
            const int ac = j0 + c - 64;
#pragma unroll
            for (int i = 0; i < 2; i++) {
                const int p = lane + 32 * i;
                const int idx = ac * 64 + ((p & 32) | ((p ^ (ac & 31)) & 31));
                F2U o; o.u = sOut2[idx];
                float mlo = fmaxf(o.f.x - sTau[p], 0.0f);
                float mhi = fmaxf(o.f.y - sTau[p + 64], 0.0f);
                o.f.x = 1.3f * sigf(glu[c][i])     * (1.0f - mlo);
                o.f.y = 1.3f * sigf(glu[c][i + 2]) * (1.0f - mhi);
                sOut2[idx] = o.u;
            }
        }
    }
}

// ---------------- pre/post kernels ----------------
__global__ void k_zero() {
    int t = threadIdx.x;
    if (t < DIMD) { g_sum[t] = 0.0f; g_sumsq[t] = 0.0f; }
    if (t == 0) g_mloss = 0.0f;
}

__global__ void k_stats(const float* __restrict__ x) {
    const int col = threadIdx.x;
    const int rb  = blockIdx.x * 128;
    float s = 0.0f, sq = 0.0f;
#pragma unroll 4
    for (int r = 0; r < 128; r++) {
        float v = x[(size_t)(rb + r) * DIMD + col];
        s += v; sq = fmaf(v, v, sq);
    }
    atomicAdd(&g_sum[col], s);
    atomicAdd(&g_sumsq[col], sq);
}

__global__ void k_xn(const float* __restrict__ x,
                     const float* __restrict__ gam,
                     const float* __restrict__ bet) {
    const int i4 = blockIdx.x * blockDim.x + threadIdx.x;
    const int c4 = (i4 & 31) << 2;
    float4 xv = ((const float4*)x)[i4];
    float o[4] = {xv.x, xv.y, xv.z, xv.w};
    const float inv = 1.0f / (float)BATCH;
#pragma unroll
    for (int j = 0; j < 4; j++) {
        const int c = c4 + j;
        float mean = g_sum[c] * inv;
        float var  = g_sumsq[c] * inv - mean * mean;
        float rs   = rsqrtf(var + BN_EPS);
        o[j] = (o[j] - mean) * rs * gam[c] + bet[c];
    }
    ((float4*)g_xn)[i4] = make_float4(o[0], o[1], o[2], o[3]);
}

// Pack + duplicate weights: per (step s, group g, k): 16 floats
// {wa0,wa0,wa1,wa1,...,wg0,wg0,...} where wa_c = W[4g+c][k], wg_c = W[4g+c+192][k]
__global__ void k_wpack(const float* __restrict__ W, int off, int K) {
    const int s = blockIdx.x / 48, g = blockIdx.x % 48;
    const float* Ws = W + (size_t)s * 384 * K;
    float* os = g_wp + off + (size_t)blockIdx.x * K * 16;
    for (int idx = threadIdx.x; idx < K * 16; idx += blockDim.x) {
        const int k = idx >> 4, m = idx & 15;
        const int half = m >> 3, c = (m & 7) >> 1;
        os[idx] = Ws[(size_t)(4 * g + c + 192 * half) * K + k];
    }
}

__global__ void k_fin(float* __restrict__ outp) {
    outp[(size_t)NSTEPS * BATCH * 64] = g_mloss * (1.0f / ((float)BATCH * (float)NSTEPS));
}

// ---------------- fused main kernel: one CTA = one 128-row GBN chunk ----------------
#define SMEM_FLOATS (16384 + 16384 + 24576 + 128)
#define SMEM_BYTES  (SMEM_FLOATS * 4)

__global__ void __launch_bounds__(512, 1) tabnet_main(
    const float* __restrict__ encg0, const float* __restrict__ encb0,
    const float* __restrict__ encg1, const float* __restrict__ encb1,
    const float* __restrict__ decg0, const float* __restrict__ decb0,
    const float* __restrict__ decg1, const float* __restrict__ decb1,
    float* __restrict__ outp)
{
    extern __shared__ float sm[];
    float* sMxF  = sm;            // [128 k][64 pairs * 2] masked_x, row-paired swizzled
    float* sAttF = sm + 16384;    // same layout, att
    float* sH1F  = sm + 32768;    // [192 k][128] GLU1 out, row-paired swizzled
    float* sTau  = sm + 57344;    // [128]
    u64t* sMx2  = (u64t*)sMxF;
    u64t* sAtt2 = (u64t*)sAttF;
    u64t* sH12  = (u64t*)sH1F;

    const int t = threadIdx.x, lane = t & 31, w = t >> 5;
    const int chunk = blockIdx.x;

    for (int i = t; i < 16384; i += 512) sAttF[i] = 1.0f;   // prior stays 1
    __syncthreads();

    float mloss = 0.0f;
    const float* xrow = g_xn + (size_t)chunk * 128 * DIMD;

    for (int s = 0; s < NSTEPS; s++) {
        // ---- fused sparsemax tau (Michelot, exact) + mask + M_loss ----
        for (int rr = 0; rr < 8; rr++) {
            const int row = w * 8 + rr;
            const int p = row & 63, h = row >> 6;
            const int zoff = 2 * ((p & 32) | ((p ^ lane) & 31)) + h;
            float z[4];
#pragma unroll
            for (int c = 0; c < 4; c++)
                z[c] = sAttF[(lane + 32 * c) * 128 + zoff];
            float mx = wmax(fmaxf(fmaxf(z[0], z[1]), fmaxf(z[2], z[3])));
#pragma unroll
            for (int c = 0; c < 4; c++) z[c] -= mx;
            float tau = (wsum(z[0] + z[1] + z[2] + z[3]) - 1.0f) * (1.0f / 128.0f);
            for (int it = 0; it < 32; it++) {
                float sp = 0.0f, kp = 0.0f;
#pragma unroll
                for (int c = 0; c < 4; c++)
                    if (z[c] > tau) { sp += z[c]; kp += 1.0f; }
                sp = wsum(sp); kp = wsum(kp);
                float tn = (sp - 1.0f) / kp;
                if (tn == tau) break;
                tau = tn;
            }
            if (lane == 0) sTau[row] = tau + mx;   // full-scale tau for MODE 2
#pragma unroll
            for (int c = 0; c < 4; c++) {
                const int col = lane + 32 * c;
                float m = fmaxf(z[c] - tau, 0.0f);
                float xv = xrow[row * DIMD + col];
                sMxF[col * 128 + zoff] = m * xv;
                mloss += m * __logf(m + 1e-10f);
            }
        }
        __syncthreads();

        if (s < NSTEPS - 1) {
            // encoder GLU1
            {
                const float* base = g_wp + OFF_E0 + (size_t)(s * 48) * 128 * 16;
#pragma unroll 1
                for (int pp = 0; pp < 3; pp++) {
                    const int g = pp * 16 + w;
                    glu_pass<128, 0>(sMx2, (const ulonglong2*)(base + (size_t)g * 128 * 16),
                                     encg0, encb0, 4 * g, lane, sH12, sTau, nullptr);
                }
            }
            __syncthreads();
            // encoder GLU2 -> att update (only cols 64..191 matter)
            {
                const float* base = g_wp + OFF_E1 + (size_t)(s * 48) * 192 * 16;
#pragma unroll 1
                for (int pp = 0; pp < 2; pp++) {
                    const int g = 16 + pp * 16 + w;
                    glu_pass<192, 2>(sH12, (const ulonglong2*)(base + (size_t)g * 192 * 16),
                                     encg1, encb1, 4 * g, lane, sAtt2, sTau, nullptr);
                }
            }
            __syncthreads();
        }
        // decoder GLU1
        {
            const float* base = g_wp + OFF_D0 + (size_t)(s * 48) * 128 * 16;
#pragma unroll 1
            for (int pp = 0; pp < 3; pp++) {
                const int g = pp * 16 + w;
                glu_pass<128, 0>(sMx2, (const ulonglong2*)(base + (size_t)g * 128 * 16),
                                 decg0, decb0, 4 * g, lane, sH12, sTau, nullptr);
            }
        }
        __syncthreads();
        // decoder GLU2 -> sigmoid output (only cols 0..63)
        {
            const float* base = g_wp + OFF_D1 + (size_t)(s * 48) * 192 * 16;
            float* ob = outp + ((size_t)s * BATCH + (size_t)chunk * 128) * 64;
            const int g = w;
            glu_pass<192, 1>(sH12, (const ulonglong2*)(base + (size_t)g * 192 * 16),
                             decg1, decb1, 4 * g, lane, nullptr, sTau, ob);
        }
        __syncthreads();
    }

    mloss = wsum(mloss);
    if (lane == 0) atomicAdd(&g_mloss, mloss);
}

// ---------------- launch ----------------
extern "C" void kernel_launch(void* const* d_in, const int* in_sizes, int n_in,
                              void* d_out, int out_size) {
    const float* x     = (const float*)d_in[0];
    const float* ig    = (const float*)d_in[1];
    const float* ib    = (const float*)d_in[2];
    const float* encW0 = (const float*)d_in[3];
    const float* encg0 = (const float*)d_in[4];
    const float* encb0 = (const float*)d_in[5];
    const float* encW1 = (const float*)d_in[6];
    const float* encg1 = (const float*)d_in[7];
    const float* encb1 = (const float*)d_in[8];
    const float* decW0 = (const float*)d_in[9];
    const float* decg0 = (const float*)d_in[10];
    const float* decb0 = (const float*)d_in[11];
    const float* decW1 = (const float*)d_in[12];
    const float* decg1 = (const float*)d_in[13];
    const float* decb1 = (const float*)d_in[14];
    float* out = (float*)d_out;

    cudaFuncSetAttribute(tabnet_main, cudaFuncAttributeMaxDynamicSharedMemorySize, SMEM_BYTES);

    k_zero<<<1, 128>>>();
    k_stats<<<BATCH / 128, 128>>>(x);
    k_xn<<<(BATCH * DIMD / 4) / 256, 256>>>(x, ig, ib);
    k_wpack<<<144, 128>>>(encW0, OFF_E0, 128);
    k_wpack<<<144, 128>>>(encW1, OFF_E1, 192);
    k_wpack<<<144, 128>>>(decW0, OFF_D0, 128);
    k_wpack<<<144, 128>>>(decW1, OFF_D1, 192);
    tabnet_main<<<BATCH / 128, 512, SMEM_BYTES>>>(
        encg0, encb0, encg1, encb1,
        decg0, decb0, decg1, decb1, out);
    k_fin<<<1, 1>>>(out);
}

// round 6
// speedup vs baseline: 1.6647x; 1.6647x over previous
#include <cuda_runtime.h>
#include <cuda_bf16.h>
#include <cstdint>

#define BATCH   32768
#define DIMD    128
#define NSTEPS  3
#define BN_EPS  1e-5f
#define FULLM   0xffffffffu

typedef unsigned long long u64t;
union F2U { u64t u; float2 f; };

// fma.rn.f32x2: two independent fp32 FMAs in one instruction (sm_100+)
#define FMA2(acc, a, b) asm("fma.rn.f32x2 %0, %1, %2, %0;" : "+l"(acc) : "l"(a), "l"(b))

// ---------------- device scratch (no allocations allowed) ----------------
__device__ float g_sum[DIMD];
__device__ float g_sumsq[DIMD];
__device__ float g_mloss;
__device__ float g_xn[(size_t)BATCH * DIMD];      // normalized input (16 MB)
__device__ __align__(16) float g_wp[516096];      // packed {wa,wg}-paired weights (2 MB)

// float offsets into g_wp
#define OFF_E0 0
#define OFF_E1 147456
#define OFF_D0 294912
#define OFF_D1 442368

// ---------------- helpers ----------------
__device__ __forceinline__ float wsum(float v) {
#pragma unroll
    for (int o = 16; o > 0; o >>= 1) v += __shfl_xor_sync(FULLM, v, o);
    return v;
}
__device__ __forceinline__ float wmax(float v) {
#pragma unroll
    for (int o = 16; o > 0; o >>= 1) v = fmaxf(v, __shfl_xor_sync(FULLM, v, o));
    return v;
}
__device__ __forceinline__ float sigf(float x) {
    return 1.0f / (1.0f + __expf(-x));
}

// ---------------- GLU GEMM + GhostBN building block ----------------
// One warp computes 4 GLU pairs (a-col j, gate-col j+192) for j=j0..j0+3 over all
// 128 rows. Lane owns rows {lane, lane+32, lane+64, lane+96}.
// Accumulator = f32x2 {a_acc, g_acc}; weights arrive pre-paired {wa,wg}:
//   packed layout per group: [k][pair 0..3][{wa,wg}]  (8 floats per k, contiguous)
// Lane l preloads the full slab row k=k0+l (4 u64 = 2 LDG.128, coalesced);
// per-k distribution via 4x 64-bit shfl (result is directly FMA2's B operand).
// Activations: sA[k*128 + (row ^ (k&31))], conflict-free; duplicated {x,x} per row.
// MODE 0: write GLU out to sOut  (layout [j][row ^ (j&31)])
// MODE 1: write sigmoid(GLU out) to global outp (decoder final, cols 0..63)
// MODE 2: att update in sOut: att = 1.3*sig(o)*(1 - max(att_old - tau, 0))
template<int K, int MODE>
__device__ __forceinline__ void glu_pass(
    const float* __restrict__ sA,
    const float* __restrict__ wpg,   // group base in g_wp
    const float* __restrict__ gv, const float* __restrict__ bv,
    int j0, int lane,
    float* __restrict__ sOut, const float* __restrict__ sTau,
    float* __restrict__ outp)
{
    u64t acc[4][4];                  // [pair][row]: {a_acc, g_acc}
#pragma unroll
    for (int p = 0; p < 4; p++)
#pragma unroll
        for (int r = 0; r < 4; r++) acc[p][r] = 0ull;

    const ulonglong2* wp2 = (const ulonglong2*)wpg;   // 2 x ulonglong2 per k
    ulonglong2 cA = __ldg(wp2 + lane * 2);
    ulonglong2 cB = __ldg(wp2 + lane * 2 + 1);

#pragma unroll 1
    for (int k0 = 0; k0 < K; k0 += 32) {
        ulonglong2 nA, nB;
        if (k0 + 32 < K) {
            nA = __ldg(wp2 + (k0 + 32 + lane) * 2);
            nB = __ldg(wp2 + (k0 + 32 + lane) * 2 + 1);
        } else { nA = cA; nB = cB; }

#pragma unroll
        for (int kk = 0; kk < 32; kk++) {
            const int k = k0 + kk;                    // k & 31 == kk
            u64t w0 = __shfl_sync(FULLM, cA.x, kk);
            u64t w1 = __shfl_sync(FULLM, cA.y, kk);
            u64t w2 = __shfl_sync(FULLM, cB.x, kk);
            u64t w3 = __shfl_sync(FULLM, cB.y, kk);
            const int a0 = k * 128 + (lane ^ kk);     // +32r folds into immediates
#pragma unroll
            for (int r = 0; r < 4; r++) {
                float x = sA[a0 + 32 * r];
                F2U a; a.f.x = x; a.f.y = x;
                FMA2(acc[0][r], a.u, w0);
                FMA2(acc[1][r], a.u, w1);
                FMA2(acc[2][r], a.u, w2);
                FMA2(acc[3][r], a.u, w3);
            }
        }
        cA = nA; cB = nB;
    }

    // ---- epilogue: Ghost-BN per column (warp allreduce over 128 rows) + GLU ----
    float glu[4][4];
#pragma unroll
    for (int p = 0; p < 4; p++) {
        const int j = j0 + p;
        float av[4], gvl[4];
#pragma unroll
        for (int r = 0; r < 4; r++) { F2U t; t.u = acc[p][r]; av[r] = t.f.x; gvl[r] = t.f.y; }
        float s = wsum(av[0] + av[1] + av[2] + av[3]);
        float mean = s * (1.0f / 128.0f);
        float d0 = av[0]-mean, d1 = av[1]-mean, d2 = av[2]-mean, d3 = av[3]-mean;
        float v = wsum(d0*d0 + d1*d1 + d2*d2 + d3*d3);
        float rstd = rsqrtf(v * (1.0f / 128.0f) + BN_EPS);
        float ga = __ldg(gv + j) * rstd, ba = __ldg(bv + j);
        float s2 = wsum(gvl[0] + gvl[1] + gvl[2] + gvl[3]);
        float mean2 = s2 * (1.0f / 128.0f);
        float e0 = gvl[0]-mean2, e1 = gvl[1]-mean2, e2 = gvl[2]-mean2, e3 = gvl[3]-mean2;
        float v2 = wsum(e0*e0 + e1*e1 + e2*e2 + e3*e3);
        float rstd2 = rsqrtf(v2 * (1.0f / 128.0f) + BN_EPS);
        float gg = __ldg(gv + j + 192) * rstd2, bg = __ldg(bv + j + 192);
        glu[p][0] = (d0 * ga + ba) * sigf(e0 * gg + bg);
        glu[p][1] = (d1 * ga + ba) * sigf(e1 * gg + bg);
        glu[p][2] = (d2 * ga + ba) * sigf(e2 * gg + bg);
        glu[p][3] = (d3 * ga + ba) * sigf(e3 * gg + bg);
    }

    if (MODE == 0) {
#pragma unroll
        for (int p = 0; p < 4; p++) {
            const int j = j0 + p;
#pragma unroll
            for (int r = 0; r < 4; r++) {
                const int row = lane + 32 * r;
                sOut[j * 128 + (row ^ (j & 31))] = glu[p][r];
            }
        }
    } else if (MODE == 1) {
#pragma unroll
        for (int r = 0; r < 4; r++) {
            const int row = lane + 32 * r;
            float4 o = make_float4(sigf(glu[0][r]), sigf(glu[1][r]),
                                   sigf(glu[2][r]), sigf(glu[3][r]));
            *(float4*)(outp + (size_t)row * 64 + j0) = o;
        }
    } else { // MODE 2: att update (att layout [row][col ^ (row&31)])
#pragma unroll
        for (int p = 0; p < 4; p++) {
            const int ac = j0 + p - 64;
#pragma unroll
            for (int r = 0; r < 4; r++) {
                const int row = lane + 32 * r;
                const int idx = row * 128 + (ac ^ (row & 31));
                float old = sOut[idx];
                float m = fmaxf(old - sTau[row], 0.0f);
                sOut[idx] = 1.3f * sigf(glu[p][r]) * (1.0f - m);
            }
        }
    }
}

// ---------------- pre/post kernels ----------------
__global__ void k_zero() {
    int t = threadIdx.x;
    if (t < DIMD) { g_sum[t] = 0.0f; g_sumsq[t] = 0.0f; }
    if (t == 0) g_mloss = 0.0f;
}

__global__ void k_stats(const float* __restrict__ x) {
    const int col = threadIdx.x;
    const int rb  = blockIdx.x * 128;
    float s = 0.0f, sq = 0.0f;
#pragma unroll 4
    for (int r = 0; r < 128; r++) {
        float v = x[(size_t)(rb + r) * DIMD + col];
        s += v; sq = fmaf(v, v, sq);
    }
    atomicAdd(&g_sum[col], s);
    atomicAdd(&g_sumsq[col], sq);
}

__global__ void k_xn(const float* __restrict__ x,
                     const float* __restrict__ gam,
                     const float* __restrict__ bet) {
    const int i4 = blockIdx.x * blockDim.x + threadIdx.x;
    const int c4 = (i4 & 31) << 2;
    float4 xv = ((const float4*)x)[i4];
    float o[4] = {xv.x, xv.y, xv.z, xv.w};
    const float inv = 1.0f / (float)BATCH;
#pragma unroll
    for (int j = 0; j < 4; j++) {
        const int c = c4 + j;
        float mean = g_sum[c] * inv;
        float var  = g_sumsq[c] * inv - mean * mean;
        float rs   = rsqrtf(var + BN_EPS);
        o[j] = (o[j] - mean) * rs * gam[c] + bet[c];
    }
    ((float4*)g_xn)[i4] = make_float4(o[0], o[1], o[2], o[3]);
}

// Pack weights pair-interleaved: per (step s, group g): [k][p 0..3][{wa,wg}]
// wa = W[pairbase+4g+p][k], wg = W[pairbase+4g+p+192][k]
__device__ __forceinline__ void wpack_one(const float* W, int off, int K,
                                          int ngroups, int pairbase, int b, int tid, int nt) {
    const int s = b / ngroups, g = b % ngroups;
    const float* Ws = W + (size_t)s * 384 * K;
    float* os = g_wp + off + (size_t)(s * ngroups + g) * K * 8;
    for (int idx = tid; idx < K * 8; idx += nt) {
        const int k = idx >> 3, m = idx & 7, p = m >> 1, h = m & 1;
        os[idx] = Ws[(size_t)(pairbase + 4 * g + p + 192 * h) * K + k];
    }
}

// one combined pack launch: 432 blocks
__global__ void k_wpack(const float* __restrict__ e0, const float* __restrict__ e1,
                        const float* __restrict__ d0, const float* __restrict__ d1) {
    int b = blockIdx.x, t = threadIdx.x, nt = blockDim.x;
    if (b < 144)      wpack_one(e0, OFF_E0, 128, 48, 0,  b,       t, nt);
    else if (b < 240) wpack_one(e1, OFF_E1, 192, 32, 64, b - 144, t, nt);
    else if (b < 384) wpack_one(d0, OFF_D0, 128, 48, 0,  b - 240, t, nt);
    else              wpack_one(d1, OFF_D1, 192, 16, 0,  b - 384, t, nt);
}

__global__ void k_fin(float* __restrict__ outp) {
    outp[(size_t)NSTEPS * BATCH * 64] = g_mloss * (1.0f / ((float)BATCH * (float)NSTEPS));
}

// ---------------- fused main kernel: one CTA = one 128-row GBN chunk ----------------
#define SMEM_FLOATS (16384 + 16384 + 24576 + 128)
#define SMEM_BYTES  (SMEM_FLOATS * 4)

__global__ void __launch_bounds__(512, 1) tabnet_main(
    const float* __restrict__ encg0, const float* __restrict__ encb0,
    const float* __restrict__ encg1, const float* __restrict__ encb1,
    const float* __restrict__ decg0, const float* __restrict__ decb0,
    const float* __restrict__ decg1, const float* __restrict__ decb1,
    float* __restrict__ outp)
{
    extern __shared__ float sm[];
    float* sMx  = sm;             // [128 k][128 row^k&31]  masked_x (transposed)
    float* sAtt = sm + 16384;     // [128 row][128 col^row&31] att
    float* sH1  = sm + 32768;     // [192 j][128 row^j&31]  GLU1 out (transposed)
    float* sTau = sm + 57344;     // [128]

    const int t = threadIdx.x, lane = t & 31, w = t >> 5;
    const int chunk = blockIdx.x;

    for (int i = t; i < 16384; i += 512) sAtt[i] = 1.0f;   // prior stays 1
    __syncthreads();

    float mloss = 0.0f;
    const float* xrow = g_xn + (size_t)chunk * 128 * DIMD;

    for (int s = 0; s < NSTEPS; s++) {
        // ---- fused sparsemax tau (Michelot, exact) + mask + M_loss ----
        for (int rr = 0; rr < 8; rr++) {
            const int row = w * 8 + rr;
            float z[4];
#pragma unroll
            for (int c = 0; c < 4; c++) {
                const int col = lane + 32 * c;
                z[c] = sAtt[row * 128 + (col ^ (row & 31))];
            }
            float mx = wmax(fmaxf(fmaxf(z[0], z[1]), fmaxf(z[2], z[3])));
#pragma unroll
            for (int c = 0; c < 4; c++) z[c] -= mx;
            float tau = (wsum(z[0] + z[1] + z[2] + z[3]) - 1.0f) * (1.0f / 128.0f);
            for (int it = 0; it < 32; it++) {
                float sp = 0.0f, kp = 0.0f;
#pragma unroll
                for (int c = 0; c < 4; c++)
                    if (z[c] > tau) { sp += z[c]; kp += 1.0f; }
                sp = wsum(sp); kp = wsum(kp);
                float tn = (sp - 1.0f) / kp;
                if (tn == tau) break;
                tau = tn;
            }
            if (lane == 0) sTau[row] = tau + mx;   // full-scale tau for MODE 2
#pragma unroll
            for (int c = 0; c < 4; c++) {
                const int col = lane + 32 * c;
                float m = fmaxf(z[c] - tau, 0.0f);
                float xv = xrow[row * DIMD + col];
                sMx[col * 128 + (row ^ (col & 31))] = m * xv;
                mloss += m * __logf(m + 1e-10f);
            }
        }
        __syncthreads();

        if (s < NSTEPS - 1) {
            // encoder GLU1: 48 groups = 3 passes x 16 warps
#pragma unroll 1
            for (int pp = 0; pp < 3; pp++) {
                const int g = pp * 16 + w;
                glu_pass<128, 0>(sMx, g_wp + OFF_E0 + (size_t)(s * 48 + g) * 128 * 8,
                                 encg0, encb0, 4 * g, lane, sH1, sTau, nullptr);
            }
            __syncthreads();
            // encoder GLU2 -> att update (pairs 64..191): 32 groups = 2 passes
#pragma unroll 1
            for (int pp = 0; pp < 2; pp++) {
                const int g = pp * 16 + w;
                glu_pass<192, 2>(sH1, g_wp + OFF_E1 + (size_t)(s * 32 + g) * 192 * 8,
                                 encg1, encb1, 64 + 4 * g, lane, sAtt, sTau, nullptr);
            }
            __syncthreads();
        }
        // decoder GLU1: 48 groups = 3 passes
#pragma unroll 1
        for (int pp = 0; pp < 3; pp++) {
            const int g = pp * 16 + w;
            glu_pass<128, 0>(sMx, g_wp + OFF_D0 + (size_t)(s * 48 + g) * 128 * 8,
                             decg0, decb0, 4 * g, lane, sH1, sTau, nullptr);
        }
        __syncthreads();
        // decoder GLU2 -> sigmoid output (pairs 0..63): 16 groups = 1 pass
        {
            float* ob = outp + ((size_t)s * BATCH + (size_t)chunk * 128) * 64;
            glu_pass<192, 1>(sH1, g_wp + OFF_D1 + (size_t)(s * 16 + w) * 192 * 8,
                             decg1, decb1, 4 * w, lane, nullptr, sTau, ob);
        }
        __syncthreads();
    }

    mloss = wsum(mloss);
    if (lane == 0) atomicAdd(&g_mloss, mloss);
}

// ---------------- launch ----------------
extern "C" void kernel_launch(void* const* d_in, const int* in_sizes, int n_in,
                              void* d_out, int out_size) {
    const float* x     = (const float*)d_in[0];
    const float* ig    = (const float*)d_in[1];
    const float* ib    = (const float*)d_in[2];
    const float* encW0 = (const float*)d_in[3];
    const float* encg0 = (const float*)d_in[4];
    const float* encb0 = (const float*)d_in[5];
    const float* encW1 = (const float*)d_in[6];
    const float* encg1 = (const float*)d_in[7];
    const float* encb1 = (const float*)d_in[8];
    const float* decW0 = (const float*)d_in[9];
    const float* decg0 = (const float*)d_in[10];
    const float* decb0 = (const float*)d_in[11];
    const float* decW1 = (const float*)d_in[12];
    const float* decg1 = (const float*)d_in[13];
    const float* decb1 = (const float*)d_in[14];
    float* out = (float*)d_out;

    cudaFuncSetAttribute(tabnet_main, cudaFuncAttributeMaxDynamicSharedMemorySize, SMEM_BYTES);

    k_zero<<<1, 128>>>();
    k_stats<<<BATCH / 128, 128>>>(x);
    k_xn<<<(BATCH * DIMD / 4) / 256, 256>>>(x, ig, ib);
    k_wpack<<<432, 128>>>(encW0, encW1, decW0, decW1);
    tabnet_main<<<BATCH / 128, 512, SMEM_BYTES>>>(
        encg0, encb0, encg1, encb1,
        decg0, decb0, decg1, decb1, out);
    k_fin<<<1, 1>>>(out);
}